// round 11
// baseline (speedup 1.0000x reference)
#include <cuda_runtime.h>

// Problem constants
#define BB   8
#define NN   1025
#define DD   768
#define HH   12
#define HD   64
#define EE   2304            // 3*DD
#define MR   (BB*NN)         // 8200 rows
#define LNEPS 1e-5f

// Scratch (device globals: no allocation allowed)
__device__ float g_xn [MR*DD];
__device__ float g_q  [BB*HH*NN*HD];
__device__ float g_k  [BB*HH*NN*HD];
__device__ float g_v  [BB*HH*NN*HD];
__device__ float g_att[MR*DD];
__device__ float g_wq [EE*DD];       // tf32-rounded w_qkv
__device__ float g_wp [DD*DD];       // tf32-rounded w_proj

// ---------------------------------------------------------------------------
// helpers
// ---------------------------------------------------------------------------
__device__ __forceinline__ float f2tf32(float f) {
    unsigned u;
    asm("cvt.rna.tf32.f32 %0, %1;" : "=r"(u) : "f"(f));
    return __uint_as_float(u);
}

__device__ __forceinline__ void mma_tf32(float& d0, float& d1, float& d2, float& d3,
                                         unsigned a0, unsigned a1, unsigned a2, unsigned a3,
                                         unsigned b0, unsigned b1) {
    asm volatile(
        "mma.sync.aligned.m16n8k8.row.col.f32.tf32.tf32.f32 "
        "{%0,%1,%2,%3},{%4,%5,%6,%7},{%8,%9},{%0,%1,%2,%3};"
        : "+f"(d0), "+f"(d1), "+f"(d2), "+f"(d3)
        : "r"(a0), "r"(a1), "r"(a2), "r"(a3), "r"(b0), "r"(b1));
}

__device__ __forceinline__ void cpa16(const void* smemp, const void* g, bool pred) {
    unsigned sa = (unsigned)__cvta_generic_to_shared(smemp);
    int sz = pred ? 16 : 0;
    asm volatile("cp.async.cg.shared.global [%0], [%1], 16, %2;"
                 :: "r"(sa), "l"(g), "r"(sz));
}
#define CP_COMMIT() asm volatile("cp.async.commit_group;")
#define CP_WAIT(n)  asm volatile("cp.async.wait_group %0;" :: "n"(n))

// ---------------------------------------------------------------------------
// 0. Pre-round weights to tf32 (vectorized)
// ---------------------------------------------------------------------------
__global__ void roundw_kernel(const float4* __restrict__ wq,
                              const float4* __restrict__ wp) {
    const int NQ = EE*DD/4, NP = DD*DD/4;
    int i = blockIdx.x * 256 + threadIdx.x;
    if (i < NQ) {
        float4 v = wq[i];
        v.x = f2tf32(v.x); v.y = f2tf32(v.y); v.z = f2tf32(v.z); v.w = f2tf32(v.w);
        ((float4*)g_wq)[i] = v;
    } else if (i - NQ < NP) {
        int j = i - NQ;
        float4 v = wp[j];
        v.x = f2tf32(v.x); v.y = f2tf32(v.y); v.z = f2tf32(v.z); v.w = f2tf32(v.w);
        ((float4*)g_wp)[j] = v;
    }
}

// ---------------------------------------------------------------------------
// 1. LayerNorm: one block (256 thr) per row; tf32-rounded output
// ---------------------------------------------------------------------------
__global__ void ln_kernel(const float* __restrict__ x,
                          const float* __restrict__ gam,
                          const float* __restrict__ bet) {
    int row = blockIdx.x;
    const float* xr = x + (size_t)row * DD;
    float* outr = g_xn + (size_t)row * DD;
    int t = threadIdx.x;
    float v0 = xr[t], v1 = xr[t+256], v2 = xr[t+512];
    float s  = v0+v1+v2;
    float sq = v0*v0 + v1*v1 + v2*v2;
    #pragma unroll
    for (int o = 16; o; o >>= 1) {
        s  += __shfl_xor_sync(0xffffffffu, s,  o);
        sq += __shfl_xor_sync(0xffffffffu, sq, o);
    }
    __shared__ float rs[8], rq[8];
    int w = t >> 5, l = t & 31;
    if (!l) { rs[w] = s; rq[w] = sq; }
    __syncthreads();
    if (w == 0) {
        s  = (l < 8) ? rs[l] : 0.f;
        sq = (l < 8) ? rq[l] : 0.f;
        #pragma unroll
        for (int o = 4; o; o >>= 1) {
            s  += __shfl_xor_sync(0xffffffffu, s,  o);
            sq += __shfl_xor_sync(0xffffffffu, sq, o);
        }
        if (!l) { rs[0] = s * (1.f/DD); rq[0] = sq * (1.f/DD); }
    }
    __syncthreads();
    float mu = rs[0];
    float var = rq[0] - mu*mu;
    float rstd = rsqrtf(var + LNEPS);
    outr[t]     = f2tf32((v0-mu)*rstd*gam[t]     + bet[t]);
    outr[t+256] = f2tf32((v1-mu)*rstd*gam[t+256] + bet[t+256]);
    outr[t+512] = f2tf32((v2-mu)*rstd*gam[t+512] + bet[t+512]);
}

// ---------------------------------------------------------------------------
// 2. TF32 tensor-core NT GEMM: 256x128 block tile, 8 warps (4 row x 2 col),
//    warp tile 64x64 (mt=4, nt=8), k-step 16, cp.async double-buffered.
//    MODE 0: QKV — fused RoPE epilogue, scatter to g_q/g_k/g_v
//    MODE 1: proj — +bias, write C
//    Dynamic smem: As[2][256][20], Ws[2][128][20], (+ cos/sin tables in MODE 0)
// ---------------------------------------------------------------------------
template<int M, int NC, int K, int MODE>
__device__ __forceinline__ void gemm_mma_body(const float* __restrict__ A,
                                              const float* __restrict__ W,
                                              const float* __restrict__ bias,
                                              float* __restrict__ C) {
    extern __shared__ float smf[];
    float (*As)[20] = (float(*)[20])smf;                 // [2*256][20]
    float (*Ws)[20] = (float(*)[20])(smf + 2*256*20);    // [2*128][20]
    float* cs_tab = smf + 2*256*20 + 2*128*20;           // [32*16]
    float* sn_tab = cs_tab + 512;

    int tid = threadIdx.x;
    int w = tid >> 5, lane = tid & 31;
    int wm = w & 3;          // row quadrant: 64*wm
    int wn = w >> 2;         // col half:    64*wn
    int g  = lane >> 2;
    int tg = lane & 3;
    int rowBase = blockIdx.x * 256;
    int colBase = blockIdx.y * 128;

    if (MODE == 0) {
        // 256 threads -> 512 entries: each thread writes 2 (R9 bug: tid<512 with 256 threads)
        #pragma unroll
        for (int i = tid; i < 512; i += 256) {
            int t = i >> 4, j = i & 15;
            float th = (float)t * expf(-(float)j * 0.5756462732485115f);
            float sv, cv;
            sincosf(th, &sv, &cv);
            cs_tab[i] = cv; sn_tab[i] = sv;
        }
    }

    float acc[4][8][4] = {};

    auto stage = [&](int buf, int kt) {
        #pragma unroll
        for (int s = 0; s < 4; s++) {
            int lin = tid + s*256;
            int r = lin >> 2, c = (lin & 3)*4;
            int gr = rowBase + r;
            cpa16(&As[buf*256 + r][c], A + (size_t)gr*K + kt + c, gr < M);
        }
        #pragma unroll
        for (int s = 0; s < 2; s++) {
            int lin = tid + s*256;
            int r = lin >> 2, c = (lin & 3)*4;
            cpa16(&Ws[buf*128 + r][c], W + (size_t)(colBase + r)*K + kt + c, true);
        }
        CP_COMMIT();
    };

    stage(0, 0);
    const int NKT = K / 16;
    for (int ki = 0; ki < NKT; ki++) {
        if (ki + 1 < NKT) { stage((ki+1)&1, (ki+1)*16); CP_WAIT(1); }
        else              { CP_WAIT(0); }
        __syncthreads();
        int buf = ki & 1;
        #pragma unroll
        for (int ks = 0; ks < 16; ks += 8) {
            unsigned a[4][4], bf[8][2];
            #pragma unroll
            for (int mt = 0; mt < 4; mt++) {
                int r0 = buf*256 + wm*64 + mt*16 + g;
                a[mt][0] = __float_as_uint(As[r0  ][ks+tg  ]);
                a[mt][1] = __float_as_uint(As[r0+8][ks+tg  ]);
                a[mt][2] = __float_as_uint(As[r0  ][ks+tg+4]);
                a[mt][3] = __float_as_uint(As[r0+8][ks+tg+4]);
            }
            #pragma unroll
            for (int nt = 0; nt < 8; nt++) {
                int c0 = buf*128 + wn*64 + nt*8 + g;
                bf[nt][0] = __float_as_uint(Ws[c0][ks+tg  ]);
                bf[nt][1] = __float_as_uint(Ws[c0][ks+tg+4]);
            }
            #pragma unroll
            for (int mt = 0; mt < 4; mt++)
                #pragma unroll
                for (int nt = 0; nt < 8; nt++)
                    mma_tf32(acc[mt][nt][0], acc[mt][nt][1], acc[mt][nt][2], acc[mt][nt][3],
                             a[mt][0], a[mt][1], a[mt][2], a[mt][3],
                             bf[nt][0], bf[nt][1]);
        }
        __syncthreads();
    }

    if (MODE == 0) {
        // fused RoPE + scatter to g_q (x0.125) / g_k / g_v
        #pragma unroll
        for (int mt = 0; mt < 4; mt++) {
            #pragma unroll
            for (int half = 0; half < 2; half++) {
                int r = rowBase + wm*64 + mt*16 + g + half*8;
                if (r >= M) continue;
                int b_ = r / NN, n = r % NN;
                int rid = (n == 0) ? 0 : (n-1) >> 5;
                int cid = (n == 0) ? 0 : (n-1) & 31;
                #pragma unroll
                for (int nt = 0; nt < 8; nt++) {
                    int c = colBase + wn*64 + nt*8 + tg*2;
                    float x = acc[mt][nt][half*2+0];
                    float y = acc[mt][nt][half*2+1];
                    int which = c / 768;
                    int hd_ = c & 63;
                    int h = (c % 768) >> 6;
                    size_t o = ((size_t)(b_*HH + h)*NN + n)*64 + hd_;
                    if (which == 2) {
                        float2 ov; ov.x = f2tf32(x); ov.y = f2tf32(y);
                        *(float2*)&g_v[o] = ov;
                    } else {
                        int t = (hd_ >= 32) ? cid : rid;
                        int j = (hd_ & 31) >> 1;
                        float cv = cs_tab[t*16 + j], sv = sn_tab[t*16 + j];
                        float xe = x*cv - y*sv;
                        float yo = y*cv + x*sv;
                        if (which == 0) {
                            float2 ov;
                            ov.x = f2tf32(xe * 0.125f);
                            ov.y = f2tf32(yo * 0.125f);
                            *(float2*)&g_q[o] = ov;
                        } else {
                            float2 ov; ov.x = f2tf32(xe); ov.y = f2tf32(yo);
                            *(float2*)&g_k[o] = ov;
                        }
                    }
                }
            }
        }
    } else {
        #pragma unroll
        for (int mt = 0; mt < 4; mt++) {
            int r_lo = rowBase + wm*64 + mt*16 + g;
            int r_hi = r_lo + 8;
            #pragma unroll
            for (int nt = 0; nt < 8; nt++) {
                int c = colBase + wn*64 + nt*8 + tg*2;
                float bx = bias[c], by = bias[c+1];
                if (r_lo < M) {
                    float2 o; o.x = acc[mt][nt][0] + bx; o.y = acc[mt][nt][1] + by;
                    *(float2*)(&C[(size_t)r_lo * NC + c]) = o;
                }
                if (r_hi < M) {
                    float2 o; o.x = acc[mt][nt][2] + bx; o.y = acc[mt][nt][3] + by;
                    *(float2*)(&C[(size_t)r_hi * NC + c]) = o;
                }
            }
        }
    }
}

__global__ void __launch_bounds__(256) gemm_qkv_kernel() {
    gemm_mma_body<MR, EE, DD, 0>(g_xn, g_wq, nullptr, nullptr);
}
__global__ void __launch_bounds__(256) gemm_proj_kernel(const float* __restrict__ bias,
                                                        float* __restrict__ C) {
    gemm_mma_body<MR, DD, DD, 1>(g_att, g_wp, bias, C);
}

// ---------------------------------------------------------------------------
// 3. FlashAttention-2 style: Q tile 128 rows, 8 warps x (16 rows x 64 cols).
//    Q frags + S + softmax + P all register-resident; K/V cp.async
//    double-buffered. grid (9, 12, 8), 256 threads.
// ---------------------------------------------------------------------------
#define KSP 68                       // K pitch (floats)  - QK b-frags conflict-free
#define VSP 72                       // V pitch (floats)  - PV b-frags conflict-free
#define KVBUF (64*KSP + 64*VSP)      // floats per stage buffer = 8960
#define NKB 17
__global__ void __launch_bounds__(256) attn_kernel() {
    extern __shared__ float sm[];
    int tid = threadIdx.x;
    int w = tid >> 5, lane = tid & 31;
    int g  = lane >> 2;
    int tg = lane & 3;
    int qb = blockIdx.x, h = blockIdx.y, b = blockIdx.z;
    size_t headOff = (size_t)(b*HH + h) * NN * 64;

    // ---- stage Q tile (128x64) into buffer 0 region, pitch KSP ----
    #pragma unroll
    for (int s = 0; s < 8; s++) {
        int lin = tid + s*256;
        int r = lin >> 4, c = (lin & 15)*4;
        int n = qb*128 + r;
        cpa16(&sm[r*KSP + c], g_q + headOff + (size_t)n*64 + c, n < NN);
    }
    CP_COMMIT();
    CP_WAIT(0);
    __syncthreads();

    // ---- Q fragments to registers (rows w*16+g, w*16+g+8) ----
    unsigned qa[8][4];
    {
        int r0 = w*16 + g;
        #pragma unroll
        for (int sl = 0; sl < 8; sl++) {
            int dk = sl*8;
            qa[sl][0] = __float_as_uint(sm[ r0   *KSP + dk+tg  ]);
            qa[sl][1] = __float_as_uint(sm[(r0+8)*KSP + dk+tg  ]);
            qa[sl][2] = __float_as_uint(sm[ r0   *KSP + dk+tg+4]);
            qa[sl][3] = __float_as_uint(sm[(r0+8)*KSP + dk+tg+4]);
        }
    }
    __syncthreads();

    auto stage_kv = [&](int buf, int kb) {
        float* KsB = sm + buf*KVBUF;
        float* VsB = KsB + 64*KSP;
        #pragma unroll
        for (int s = 0; s < 4; s++) {
            int lin = tid + s*256;
            int r = lin >> 4, c = (lin & 15)*4;
            int n = kb*64 + r;
            bool ok = n < NN;
            cpa16(&KsB[r*KSP + c], g_k + headOff + (size_t)n*64 + c, ok);
            cpa16(&VsB[r*VSP + c], g_v + headOff + (size_t)n*64 + c, ok);
        }
        CP_COMMIT();
    };

    stage_kv(0, 0);

    float m0 = -1e30f, m1 = -1e30f, l0 = 0.f, l1 = 0.f;
    float acc[8][4] = {};

    for (int kb = 0; kb < NKB; kb++) {
        if (kb + 1 < NKB) { stage_kv((kb+1)&1, kb+1); CP_WAIT(1); }
        else              { CP_WAIT(0); }
        __syncthreads();
        const float* Ks = sm + (kb&1)*KVBUF;
        const float* Vs = Ks + 64*KSP;

        // ---- S = Q @ K^T (pre-scaled by 1/8 via Q) ----
        float s4[8][4] = {};
        #pragma unroll
        for (int sl = 0; sl < 8; sl++) {
            int dk = sl*8;
            #pragma unroll
            for (int nt = 0; nt < 8; nt++) {
                int c0 = nt*8 + g;
                unsigned b0 = __float_as_uint(Ks[c0*KSP + dk+tg  ]);
                unsigned b1 = __float_as_uint(Ks[c0*KSP + dk+tg+4]);
                mma_tf32(s4[nt][0], s4[nt][1], s4[nt][2], s4[nt][3],
                         qa[sl][0], qa[sl][1], qa[sl][2], qa[sl][3], b0, b1);
            }
        }

        // ---- mask last tile ----
        if (kb == NKB-1) {
            #pragma unroll
            for (int nt = 0; nt < 8; nt++) {
                int cg = (NKB-1)*64 + nt*8 + tg*2;
                if (cg   >= NN) { s4[nt][0] = -1e30f; s4[nt][2] = -1e30f; }
                if (cg+1 >= NN) { s4[nt][1] = -1e30f; s4[nt][3] = -1e30f; }
            }
        }

        // ---- online softmax in registers ----
        float mx0 = -1e30f, mx1 = -1e30f;
        #pragma unroll
        for (int nt = 0; nt < 8; nt++) {
            mx0 = fmaxf(mx0, fmaxf(s4[nt][0], s4[nt][1]));
            mx1 = fmaxf(mx1, fmaxf(s4[nt][2], s4[nt][3]));
        }
        mx0 = fmaxf(mx0, __shfl_xor_sync(0xffffffffu, mx0, 1));
        mx0 = fmaxf(mx0, __shfl_xor_sync(0xffffffffu, mx0, 2));
        mx1 = fmaxf(mx1, __shfl_xor_sync(0xffffffffu, mx1, 1));
        mx1 = fmaxf(mx1, __shfl_xor_sync(0xffffffffu, mx1, 2));
        float m0n = fmaxf(m0, mx0), m1n = fmaxf(m1, mx1);
        float al0 = __expf(m0 - m0n), al1 = __expf(m1 - m1n);
        float sum0 = 0.f, sum1 = 0.f;
        #pragma unroll
        for (int nt = 0; nt < 8; nt++) {
            float p0 = f2tf32(__expf(s4[nt][0] - m0n));
            float p1 = f2tf32(__expf(s4[nt][1] - m0n));
            float p2 = f2tf32(__expf(s4[nt][2] - m1n));
            float p3 = f2tf32(__expf(s4[nt][3] - m1n));
            sum0 += p0 + p1; sum1 += p2 + p3;
            s4[nt][0] = p0; s4[nt][1] = p1; s4[nt][2] = p2; s4[nt][3] = p3;
        }
        sum0 += __shfl_xor_sync(0xffffffffu, sum0, 1);
        sum0 += __shfl_xor_sync(0xffffffffu, sum0, 2);
        sum1 += __shfl_xor_sync(0xffffffffu, sum1, 1);
        sum1 += __shfl_xor_sync(0xffffffffu, sum1, 2);
        l0 = l0*al0 + sum0; l1 = l1*al1 + sum1;
        m0 = m0n; m1 = m1n;
        #pragma unroll
        for (int nt = 0; nt < 8; nt++) {
            acc[nt][0] *= al0; acc[nt][1] *= al0;
            acc[nt][2] *= al1; acc[nt][3] *= al1;
        }

        // ---- acc += P @ V : A-frags from registers via quad shuffles ----
        int srcA = (lane & ~3) + (tg >> 1);
        int srcB = srcA + 2;
        #pragma unroll
        for (int jt = 0; jt < 8; jt++) {
            float v00 = __shfl_sync(0xffffffffu, s4[jt][0], srcA);
            float v01 = __shfl_sync(0xffffffffu, s4[jt][1], srcA);
            float v10 = __shfl_sync(0xffffffffu, s4[jt][2], srcA);
            float v11 = __shfl_sync(0xffffffffu, s4[jt][3], srcA);
            float w00 = __shfl_sync(0xffffffffu, s4[jt][0], srcB);
            float w01 = __shfl_sync(0xffffffffu, s4[jt][1], srcB);
            float w10 = __shfl_sync(0xffffffffu, s4[jt][2], srcB);
            float w11 = __shfl_sync(0xffffffffu, s4[jt][3], srcB);
            unsigned a0 = __float_as_uint((tg & 1) ? v01 : v00);
            unsigned a1 = __float_as_uint((tg & 1) ? v11 : v10);
            unsigned a2 = __float_as_uint((tg & 1) ? w01 : w00);
            unsigned a3 = __float_as_uint((tg & 1) ? w11 : w10);
            int j0 = jt*8;
            #pragma unroll
            for (int nt = 0; nt < 8; nt++) {
                int c0 = nt*8 + g;
                unsigned b0 = __float_as_uint(Vs[(j0+tg  )*VSP + c0]);
                unsigned b1 = __float_as_uint(Vs[(j0+tg+4)*VSP + c0]);
                mma_tf32(acc[nt][0], acc[nt][1], acc[nt][2], acc[nt][3],
                         a0, a1, a2, a3, b0, b1);
            }
        }
        __syncthreads();
    }

    // ---- normalize + write (tf32-rounded for the proj GEMM) ----
    {
        int n0 = qb*128 + w*16 + g;
        int n1 = n0 + 8;
        float linv0 = 1.f / l0, linv1 = 1.f / l1;
        #pragma unroll
        for (int nt = 0; nt < 8; nt++) {
            int d = nt*8 + tg*2;
            if (n0 < NN) {
                float2 o;
                o.x = f2tf32(acc[nt][0]*linv0);
                o.y = f2tf32(acc[nt][1]*linv0);
                *(float2*)(&g_att[((size_t)b*NN + n0)*DD + h*64 + d]) = o;
            }
            if (n1 < NN) {
                float2 o;
                o.x = f2tf32(acc[nt][2]*linv1);
                o.y = f2tf32(acc[nt][3]*linv1);
                *(float2*)(&g_att[((size_t)b*NN + n1)*DD + h*64 + d]) = o;
            }
        }
    }
}

// ---------------------------------------------------------------------------
// Launch
// ---------------------------------------------------------------------------
extern "C" void kernel_launch(void* const* d_in, const int* in_sizes, int n_in,
                              void* d_out, int out_size) {
    const float* x      = (const float*)d_in[0];
    const float* ln_g   = (const float*)d_in[1];
    const float* ln_b   = (const float*)d_in[2];
    const float* w_qkv  = (const float*)d_in[3];
    const float* w_proj = (const float*)d_in[4];
    const float* b_proj = (const float*)d_in[5];
    float* out = (float*)d_out;

    const int ATT_SMEM  = 2 * KVBUF * sizeof(float);                     // 71680 B
    const int GEMM_SMEM = (2*256*20 + 2*128*20 + 2*512) * sizeof(float); // 65536 B
    cudaFuncSetAttribute(attn_kernel, cudaFuncAttributeMaxDynamicSharedMemorySize, ATT_SMEM);
    cudaFuncSetAttribute(gemm_qkv_kernel, cudaFuncAttributeMaxDynamicSharedMemorySize, GEMM_SMEM);
    cudaFuncSetAttribute(gemm_proj_kernel, cudaFuncAttributeMaxDynamicSharedMemorySize, GEMM_SMEM);

    const int RW = (EE*DD/4 + DD*DD/4 + 255) / 256;
    roundw_kernel<<<RW, 256>>>((const float4*)w_qkv, (const float4*)w_proj);
    ln_kernel<<<MR, 256>>>(x, ln_g, ln_b);
    gemm_qkv_kernel<<<dim3((MR+255)/256, EE/128), 256, GEMM_SMEM>>>();
    attn_kernel<<<dim3((NN+127)/128, HH, BB), 256, ATT_SMEM>>>();
    gemm_proj_kernel<<<dim3((MR+255)/256, DD/128), 256, GEMM_SMEM>>>(b_proj, out);
}

// round 12
// speedup vs baseline: 1.0842x; 1.0842x over previous
#include <cuda_runtime.h>

// Problem constants
#define BB   8
#define NN   1025
#define DD   768
#define HH   12
#define HD   64
#define EE   2304            // 3*DD
#define MR   (BB*NN)         // 8200 rows
#define LNEPS 1e-5f

// Scratch (device globals: no allocation allowed)
__device__ float g_xn [MR*DD];
__device__ float g_q  [BB*HH*NN*HD];
__device__ float g_k  [BB*HH*NN*HD];
__device__ float g_v  [BB*HH*NN*HD];
__device__ float g_att[MR*DD];
__device__ float g_wq [EE*DD];       // tf32-rounded w_qkv
__device__ float g_wp [DD*DD];       // tf32-rounded w_proj

// ---------------------------------------------------------------------------
// helpers
// ---------------------------------------------------------------------------
__device__ __forceinline__ float f2tf32(float f) {
    unsigned u;
    asm("cvt.rna.tf32.f32 %0, %1;" : "=r"(u) : "f"(f));
    return __uint_as_float(u);
}

__device__ __forceinline__ void mma_tf32(float& d0, float& d1, float& d2, float& d3,
                                         unsigned a0, unsigned a1, unsigned a2, unsigned a3,
                                         unsigned b0, unsigned b1) {
    asm volatile(
        "mma.sync.aligned.m16n8k8.row.col.f32.tf32.tf32.f32 "
        "{%0,%1,%2,%3},{%4,%5,%6,%7},{%8,%9},{%0,%1,%2,%3};"
        : "+f"(d0), "+f"(d1), "+f"(d2), "+f"(d3)
        : "r"(a0), "r"(a1), "r"(a2), "r"(a3), "r"(b0), "r"(b1));
}

__device__ __forceinline__ void cpa16(const void* smemp, const void* g, bool pred) {
    unsigned sa = (unsigned)__cvta_generic_to_shared(smemp);
    int sz = pred ? 16 : 0;
    asm volatile("cp.async.cg.shared.global [%0], [%1], 16, %2;"
                 :: "r"(sa), "l"(g), "r"(sz));
}
#define CP_COMMIT() asm volatile("cp.async.commit_group;")
#define CP_WAIT(n)  asm volatile("cp.async.wait_group %0;" :: "n"(n))

// ---------------------------------------------------------------------------
// 0. Pre-round weights to tf32 (vectorized)
// ---------------------------------------------------------------------------
__global__ void roundw_kernel(const float4* __restrict__ wq,
                              const float4* __restrict__ wp) {
    const int NQ = EE*DD/4, NP = DD*DD/4;
    int i = blockIdx.x * 256 + threadIdx.x;
    if (i < NQ) {
        float4 v = wq[i];
        v.x = f2tf32(v.x); v.y = f2tf32(v.y); v.z = f2tf32(v.z); v.w = f2tf32(v.w);
        ((float4*)g_wq)[i] = v;
    } else if (i - NQ < NP) {
        int j = i - NQ;
        float4 v = wp[j];
        v.x = f2tf32(v.x); v.y = f2tf32(v.y); v.z = f2tf32(v.z); v.w = f2tf32(v.w);
        ((float4*)g_wp)[j] = v;
    }
}

// ---------------------------------------------------------------------------
// 1. LayerNorm: one block (256 thr) per row; tf32-rounded output
// ---------------------------------------------------------------------------
__global__ void ln_kernel(const float* __restrict__ x,
                          const float* __restrict__ gam,
                          const float* __restrict__ bet) {
    int row = blockIdx.x;
    const float* xr = x + (size_t)row * DD;
    float* outr = g_xn + (size_t)row * DD;
    int t = threadIdx.x;
    float v0 = xr[t], v1 = xr[t+256], v2 = xr[t+512];
    float s  = v0+v1+v2;
    float sq = v0*v0 + v1*v1 + v2*v2;
    #pragma unroll
    for (int o = 16; o; o >>= 1) {
        s  += __shfl_xor_sync(0xffffffffu, s,  o);
        sq += __shfl_xor_sync(0xffffffffu, sq, o);
    }
    __shared__ float rs[8], rq[8];
    int w = t >> 5, l = t & 31;
    if (!l) { rs[w] = s; rq[w] = sq; }
    __syncthreads();
    if (w == 0) {
        s  = (l < 8) ? rs[l] : 0.f;
        sq = (l < 8) ? rq[l] : 0.f;
        #pragma unroll
        for (int o = 4; o; o >>= 1) {
            s  += __shfl_xor_sync(0xffffffffu, s,  o);
            sq += __shfl_xor_sync(0xffffffffu, sq, o);
        }
        if (!l) { rs[0] = s * (1.f/DD); rq[0] = sq * (1.f/DD); }
    }
    __syncthreads();
    float mu = rs[0];
    float var = rq[0] - mu*mu;
    float rstd = rsqrtf(var + LNEPS);
    outr[t]     = f2tf32((v0-mu)*rstd*gam[t]     + bet[t]);
    outr[t+256] = f2tf32((v1-mu)*rstd*gam[t+256] + bet[t+256]);
    outr[t+512] = f2tf32((v2-mu)*rstd*gam[t+512] + bet[t+512]);
}

// ---------------------------------------------------------------------------
// 2. TF32 tensor-core NT GEMM: 256x128 block tile, 8 warps (4 row x 2 col),
//    warp tile 64x64 (mt=4, nt=8), k-step 16, cp.async double-buffered.
//    MODE 0: QKV — fused RoPE epilogue, scatter to g_q/g_k/g_v
//    MODE 1: proj — +bias, write C
//    Dynamic smem: As[2][256][20], Ws[2][128][20], (+ cos/sin tables in MODE 0)
// ---------------------------------------------------------------------------
template<int M, int NC, int K, int MODE>
__device__ __forceinline__ void gemm_mma_body(const float* __restrict__ A,
                                              const float* __restrict__ W,
                                              const float* __restrict__ bias,
                                              float* __restrict__ C) {
    extern __shared__ float smf[];
    float (*As)[20] = (float(*)[20])smf;                 // [2*256][20]
    float (*Ws)[20] = (float(*)[20])(smf + 2*256*20);    // [2*128][20]
    float* cs_tab = smf + 2*256*20 + 2*128*20;           // [32*16]
    float* sn_tab = cs_tab + 512;

    int tid = threadIdx.x;
    int w = tid >> 5, lane = tid & 31;
    int wm = w & 3;          // row quadrant: 64*wm
    int wn = w >> 2;         // col half:    64*wn
    int g  = lane >> 2;
    int tg = lane & 3;
    int rowBase = blockIdx.x * 256;
    int colBase = blockIdx.y * 128;

    if (MODE == 0) {
        #pragma unroll
        for (int i = tid; i < 512; i += 256) {
            int t = i >> 4, j = i & 15;
            float th = (float)t * expf(-(float)j * 0.5756462732485115f);
            float sv, cv;
            sincosf(th, &sv, &cv);
            cs_tab[i] = cv; sn_tab[i] = sv;
        }
    }

    float acc[4][8][4] = {};

    auto stage = [&](int buf, int kt) {
        #pragma unroll
        for (int s = 0; s < 4; s++) {
            int lin = tid + s*256;
            int r = lin >> 2, c = (lin & 3)*4;
            int gr = rowBase + r;
            cpa16(&As[buf*256 + r][c], A + (size_t)gr*K + kt + c, gr < M);
        }
        #pragma unroll
        for (int s = 0; s < 2; s++) {
            int lin = tid + s*256;
            int r = lin >> 2, c = (lin & 3)*4;
            cpa16(&Ws[buf*128 + r][c], W + (size_t)(colBase + r)*K + kt + c, true);
        }
        CP_COMMIT();
    };

    stage(0, 0);
    const int NKT = K / 16;
    for (int ki = 0; ki < NKT; ki++) {
        if (ki + 1 < NKT) { stage((ki+1)&1, (ki+1)*16); CP_WAIT(1); }
        else              { CP_WAIT(0); }
        __syncthreads();
        int buf = ki & 1;
        #pragma unroll
        for (int ks = 0; ks < 16; ks += 8) {
            unsigned a[4][4], bf[8][2];
            #pragma unroll
            for (int mt = 0; mt < 4; mt++) {
                int r0 = buf*256 + wm*64 + mt*16 + g;
                a[mt][0] = __float_as_uint(As[r0  ][ks+tg  ]);
                a[mt][1] = __float_as_uint(As[r0+8][ks+tg  ]);
                a[mt][2] = __float_as_uint(As[r0  ][ks+tg+4]);
                a[mt][3] = __float_as_uint(As[r0+8][ks+tg+4]);
            }
            #pragma unroll
            for (int nt = 0; nt < 8; nt++) {
                int c0 = buf*128 + wn*64 + nt*8 + g;
                bf[nt][0] = __float_as_uint(Ws[c0][ks+tg  ]);
                bf[nt][1] = __float_as_uint(Ws[c0][ks+tg+4]);
            }
            #pragma unroll
            for (int mt = 0; mt < 4; mt++)
                #pragma unroll
                for (int nt = 0; nt < 8; nt++)
                    mma_tf32(acc[mt][nt][0], acc[mt][nt][1], acc[mt][nt][2], acc[mt][nt][3],
                             a[mt][0], a[mt][1], a[mt][2], a[mt][3],
                             bf[nt][0], bf[nt][1]);
        }
        __syncthreads();
    }

    if (MODE == 0) {
        // fused RoPE + scatter to g_q (x0.125) / g_k / g_v
        #pragma unroll
        for (int mt = 0; mt < 4; mt++) {
            #pragma unroll
            for (int half = 0; half < 2; half++) {
                int r = rowBase + wm*64 + mt*16 + g + half*8;
                if (r >= M) continue;
                int b_ = r / NN, n = r % NN;
                int rid = (n == 0) ? 0 : (n-1) >> 5;
                int cid = (n == 0) ? 0 : (n-1) & 31;
                #pragma unroll
                for (int nt = 0; nt < 8; nt++) {
                    int c = colBase + wn*64 + nt*8 + tg*2;
                    float x = acc[mt][nt][half*2+0];
                    float y = acc[mt][nt][half*2+1];
                    int which = c / 768;
                    int hd_ = c & 63;
                    int h = (c % 768) >> 6;
                    size_t o = ((size_t)(b_*HH + h)*NN + n)*64 + hd_;
                    if (which == 2) {
                        float2 ov; ov.x = f2tf32(x); ov.y = f2tf32(y);
                        *(float2*)&g_v[o] = ov;
                    } else {
                        int t = (hd_ >= 32) ? cid : rid;
                        int j = (hd_ & 31) >> 1;
                        float cv = cs_tab[t*16 + j], sv = sn_tab[t*16 + j];
                        float xe = x*cv - y*sv;
                        float yo = y*cv + x*sv;
                        if (which == 0) {
                            float2 ov;
                            ov.x = f2tf32(xe * 0.125f);
                            ov.y = f2tf32(yo * 0.125f);
                            *(float2*)&g_q[o] = ov;
                        } else {
                            float2 ov; ov.x = f2tf32(xe); ov.y = f2tf32(yo);
                            *(float2*)&g_k[o] = ov;
                        }
                    }
                }
            }
        }
    } else {
        #pragma unroll
        for (int mt = 0; mt < 4; mt++) {
            int r_lo = rowBase + wm*64 + mt*16 + g;
            int r_hi = r_lo + 8;
            #pragma unroll
            for (int nt = 0; nt < 8; nt++) {
                int c = colBase + wn*64 + nt*8 + tg*2;
                float bx = bias[c], by = bias[c+1];
                if (r_lo < M) {
                    float2 o; o.x = acc[mt][nt][0] + bx; o.y = acc[mt][nt][1] + by;
                    *(float2*)(&C[(size_t)r_lo * NC + c]) = o;
                }
                if (r_hi < M) {
                    float2 o; o.x = acc[mt][nt][2] + bx; o.y = acc[mt][nt][3] + by;
                    *(float2*)(&C[(size_t)r_hi * NC + c]) = o;
                }
            }
        }
    }
}

__global__ void __launch_bounds__(256) gemm_qkv_kernel() {
    gemm_mma_body<MR, EE, DD, 0>(g_xn, g_wq, nullptr, nullptr);
}
__global__ void __launch_bounds__(256) gemm_proj_kernel(const float* __restrict__ bias,
                                                        float* __restrict__ C) {
    gemm_mma_body<MR, DD, DD, 1>(g_att, g_wp, bias, C);
}

// ---------------------------------------------------------------------------
// 3. FlashAttention-2 style: Q tile 128 rows, 8 warps x (16 rows x 64 cols).
//    Q frags + S + softmax + P all register-resident; K/V cp.async
//    double-buffered. grid (9, 12, 8), 256 threads.
//    __launch_bounds__(256, 2): cap at 128 regs -> 2 CTAs/SM (was 130 -> 1 CTA).
// ---------------------------------------------------------------------------
#define KSP 68                       // K pitch (floats)  - QK b-frags conflict-free
#define VSP 72                       // V pitch (floats)  - PV b-frags conflict-free
#define KVBUF (64*KSP + 64*VSP)      // floats per stage buffer = 8960
#define NKB 17
__global__ void __launch_bounds__(256, 2) attn_kernel() {
    extern __shared__ float sm[];
    int tid = threadIdx.x;
    int w = tid >> 5, lane = tid & 31;
    int g  = lane >> 2;
    int tg = lane & 3;
    int qb = blockIdx.x, h = blockIdx.y, b = blockIdx.z;
    size_t headOff = (size_t)(b*HH + h) * NN * 64;

    // ---- stage Q tile (128x64) into buffer 0 region, pitch KSP ----
    #pragma unroll
    for (int s = 0; s < 8; s++) {
        int lin = tid + s*256;
        int r = lin >> 4, c = (lin & 15)*4;
        int n = qb*128 + r;
        cpa16(&sm[r*KSP + c], g_q + headOff + (size_t)n*64 + c, n < NN);
    }
    CP_COMMIT();
    CP_WAIT(0);
    __syncthreads();

    // ---- Q fragments to registers (rows w*16+g, w*16+g+8) ----
    unsigned qa[8][4];
    {
        int r0 = w*16 + g;
        #pragma unroll
        for (int sl = 0; sl < 8; sl++) {
            int dk = sl*8;
            qa[sl][0] = __float_as_uint(sm[ r0   *KSP + dk+tg  ]);
            qa[sl][1] = __float_as_uint(sm[(r0+8)*KSP + dk+tg  ]);
            qa[sl][2] = __float_as_uint(sm[ r0   *KSP + dk+tg+4]);
            qa[sl][3] = __float_as_uint(sm[(r0+8)*KSP + dk+tg+4]);
        }
    }
    __syncthreads();

    auto stage_kv = [&](int buf, int kb) {
        float* KsB = sm + buf*KVBUF;
        float* VsB = KsB + 64*KSP;
        #pragma unroll
        for (int s = 0; s < 4; s++) {
            int lin = tid + s*256;
            int r = lin >> 4, c = (lin & 15)*4;
            int n = kb*64 + r;
            bool ok = n < NN;
            cpa16(&KsB[r*KSP + c], g_k + headOff + (size_t)n*64 + c, ok);
            cpa16(&VsB[r*VSP + c], g_v + headOff + (size_t)n*64 + c, ok);
        }
        CP_COMMIT();
    };

    stage_kv(0, 0);

    float m0 = -1e30f, m1 = -1e30f, l0 = 0.f, l1 = 0.f;
    float acc[8][4] = {};

    for (int kb = 0; kb < NKB; kb++) {
        if (kb + 1 < NKB) { stage_kv((kb+1)&1, kb+1); CP_WAIT(1); }
        else              { CP_WAIT(0); }
        __syncthreads();
        const float* Ks = sm + (kb&1)*KVBUF;
        const float* Vs = Ks + 64*KSP;

        // ---- S = Q @ K^T (pre-scaled by 1/8 via Q) ----
        float s4[8][4] = {};
        #pragma unroll
        for (int sl = 0; sl < 8; sl++) {
            int dk = sl*8;
            #pragma unroll
            for (int nt = 0; nt < 8; nt++) {
                int c0 = nt*8 + g;
                unsigned b0 = __float_as_uint(Ks[c0*KSP + dk+tg  ]);
                unsigned b1 = __float_as_uint(Ks[c0*KSP + dk+tg+4]);
                mma_tf32(s4[nt][0], s4[nt][1], s4[nt][2], s4[nt][3],
                         qa[sl][0], qa[sl][1], qa[sl][2], qa[sl][3], b0, b1);
            }
        }

        // ---- mask last tile ----
        if (kb == NKB-1) {
            #pragma unroll
            for (int nt = 0; nt < 8; nt++) {
                int cg = (NKB-1)*64 + nt*8 + tg*2;
                if (cg   >= NN) { s4[nt][0] = -1e30f; s4[nt][2] = -1e30f; }
                if (cg+1 >= NN) { s4[nt][1] = -1e30f; s4[nt][3] = -1e30f; }
            }
        }

        // ---- online softmax in registers ----
        float mx0 = -1e30f, mx1 = -1e30f;
        #pragma unroll
        for (int nt = 0; nt < 8; nt++) {
            mx0 = fmaxf(mx0, fmaxf(s4[nt][0], s4[nt][1]));
            mx1 = fmaxf(mx1, fmaxf(s4[nt][2], s4[nt][3]));
        }
        mx0 = fmaxf(mx0, __shfl_xor_sync(0xffffffffu, mx0, 1));
        mx0 = fmaxf(mx0, __shfl_xor_sync(0xffffffffu, mx0, 2));
        mx1 = fmaxf(mx1, __shfl_xor_sync(0xffffffffu, mx1, 1));
        mx1 = fmaxf(mx1, __shfl_xor_sync(0xffffffffu, mx1, 2));
        float m0n = fmaxf(m0, mx0), m1n = fmaxf(m1, mx1);
        float al0 = __expf(m0 - m0n), al1 = __expf(m1 - m1n);
        float sum0 = 0.f, sum1 = 0.f;
        #pragma unroll
        for (int nt = 0; nt < 8; nt++) {
            float p0 = f2tf32(__expf(s4[nt][0] - m0n));
            float p1 = f2tf32(__expf(s4[nt][1] - m0n));
            float p2 = f2tf32(__expf(s4[nt][2] - m1n));
            float p3 = f2tf32(__expf(s4[nt][3] - m1n));
            sum0 += p0 + p1; sum1 += p2 + p3;
            s4[nt][0] = p0; s4[nt][1] = p1; s4[nt][2] = p2; s4[nt][3] = p3;
        }
        sum0 += __shfl_xor_sync(0xffffffffu, sum0, 1);
        sum0 += __shfl_xor_sync(0xffffffffu, sum0, 2);
        sum1 += __shfl_xor_sync(0xffffffffu, sum1, 1);
        sum1 += __shfl_xor_sync(0xffffffffu, sum1, 2);
        l0 = l0*al0 + sum0; l1 = l1*al1 + sum1;
        m0 = m0n; m1 = m1n;
        #pragma unroll
        for (int nt = 0; nt < 8; nt++) {
            acc[nt][0] *= al0; acc[nt][1] *= al0;
            acc[nt][2] *= al1; acc[nt][3] *= al1;
        }

        // ---- acc += P @ V : A-frags from registers via quad shuffles ----
        int srcA = (lane & ~3) + (tg >> 1);
        int srcB = srcA + 2;
        #pragma unroll
        for (int jt = 0; jt < 8; jt++) {
            float v00 = __shfl_sync(0xffffffffu, s4[jt][0], srcA);
            float v01 = __shfl_sync(0xffffffffu, s4[jt][1], srcA);
            float v10 = __shfl_sync(0xffffffffu, s4[jt][2], srcA);
            float v11 = __shfl_sync(0xffffffffu, s4[jt][3], srcA);
            float w00 = __shfl_sync(0xffffffffu, s4[jt][0], srcB);
            float w01 = __shfl_sync(0xffffffffu, s4[jt][1], srcB);
            float w10 = __shfl_sync(0xffffffffu, s4[jt][2], srcB);
            float w11 = __shfl_sync(0xffffffffu, s4[jt][3], srcB);
            unsigned a0 = __float_as_uint((tg & 1) ? v01 : v00);
            unsigned a1 = __float_as_uint((tg & 1) ? v11 : v10);
            unsigned a2 = __float_as_uint((tg & 1) ? w01 : w00);
            unsigned a3 = __float_as_uint((tg & 1) ? w11 : w10);
            int j0 = jt*8;
            #pragma unroll
            for (int nt = 0; nt < 8; nt++) {
                int c0 = nt*8 + g;
                unsigned b0 = __float_as_uint(Vs[(j0+tg  )*VSP + c0]);
                unsigned b1 = __float_as_uint(Vs[(j0+tg+4)*VSP + c0]);
                mma_tf32(acc[nt][0], acc[nt][1], acc[nt][2], acc[nt][3],
                         a0, a1, a2, a3, b0, b1);
            }
        }
        __syncthreads();
    }

    // ---- normalize + write (tf32-rounded for the proj GEMM) ----
    {
        int n0 = qb*128 + w*16 + g;
        int n1 = n0 + 8;
        float linv0 = 1.f / l0, linv1 = 1.f / l1;
        #pragma unroll
        for (int nt = 0; nt < 8; nt++) {
            int d = nt*8 + tg*2;
            if (n0 < NN) {
                float2 o;
                o.x = f2tf32(acc[nt][0]*linv0);
                o.y = f2tf32(acc[nt][1]*linv0);
                *(float2*)(&g_att[((size_t)b*NN + n0)*DD + h*64 + d]) = o;
            }
            if (n1 < NN) {
                float2 o;
                o.x = f2tf32(acc[nt][2]*linv1);
                o.y = f2tf32(acc[nt][3]*linv1);
                *(float2*)(&g_att[((size_t)b*NN + n1)*DD + h*64 + d]) = o;
            }
        }
    }
}

// ---------------------------------------------------------------------------
// Launch
// ---------------------------------------------------------------------------
extern "C" void kernel_launch(void* const* d_in, const int* in_sizes, int n_in,
                              void* d_out, int out_size) {
    const float* x      = (const float*)d_in[0];
    const float* ln_g   = (const float*)d_in[1];
    const float* ln_b   = (const float*)d_in[2];
    const float* w_qkv  = (const float*)d_in[3];
    const float* w_proj = (const float*)d_in[4];
    const float* b_proj = (const float*)d_in[5];
    float* out = (float*)d_out;

    const int ATT_SMEM  = 2 * KVBUF * sizeof(float);                     // 71680 B
    const int GEMM_SMEM = (2*256*20 + 2*128*20 + 2*512) * sizeof(float); // 65536 B
    cudaFuncSetAttribute(attn_kernel, cudaFuncAttributeMaxDynamicSharedMemorySize, ATT_SMEM);
    cudaFuncSetAttribute(gemm_qkv_kernel, cudaFuncAttributeMaxDynamicSharedMemorySize, GEMM_SMEM);
    cudaFuncSetAttribute(gemm_proj_kernel, cudaFuncAttributeMaxDynamicSharedMemorySize, GEMM_SMEM);

    const int RW = (EE*DD/4 + DD*DD/4 + 255) / 256;
    roundw_kernel<<<RW, 256>>>((const float4*)w_qkv, (const float4*)w_proj);
    ln_kernel<<<MR, 256>>>(x, ln_g, ln_b);
    gemm_qkv_kernel<<<dim3((MR+255)/256, EE/128), 256, GEMM_SMEM>>>();
    attn_kernel<<<dim3((NN+127)/128, HH, BB), 256, ATT_SMEM>>>();
    gemm_proj_kernel<<<dim3((MR+255)/256, DD/128), 256, GEMM_SMEM>>>(b_proj, out);
}